// round 6
// baseline (speedup 1.0000x reference)
#include <cuda_runtime.h>
#include <cstdint>

#define N_USER  100000
#define N_PHOTO 200000
#define K_IN    256
#define N_OUT   64

typedef unsigned long long ull;

// Scratch (static device globals; no allocs).
__device__ float g_Wh_user [(size_t)N_USER  * N_OUT];   // 25.6 MB
__device__ float g_Wh_photo[(size_t)N_PHOTO * N_OUT];   // 51.2 MB
__device__ float g_deg_user [N_USER];
__device__ float g_deg_photo[N_PHOTO];
__device__ ull   g_Bpack_likes  [8192];                 // packed tf32 W (64 KB)
__device__ ull   g_Bpack_likedby[8192];

__device__ __forceinline__ unsigned f2tf32(float f) {
    unsigned r;
    asm("cvt.rna.tf32.f32 %0, %1;" : "=r"(r) : "f"(f));
    return r;
}

__device__ __forceinline__ void cp_async16(unsigned dst_smem, const void* src,
                                           unsigned src_bytes) {
    asm volatile("cp.async.cg.shared.global [%0], [%1], 16, %2;"
                 :: "r"(dst_smem), "l"(src), "r"(src_bytes) : "memory");
}

// ---------------------------------------------------------------------------
// Prepack W[256,64] -> fragment-ordered tf32 ull table.
// ull index i: e = i&1; u = i>>1; t = u&3; g = (u>>2)&7; jj = (u>>5)&3; kk = u>>7.
// value = pack( tf32 W[kk*8+t][n], tf32 W[kk*8+t+4][n] ), n = (2jj+e)*8 + g.
// A warp's B fragment (kstep kk, quad t, n-pair jj) = one LDS.128 at uint4
// index kk*128 + jj*32 + g*4 + t  -> phase banks g*16+t*4: conflict-FREE.
// ---------------------------------------------------------------------------
__global__ __launch_bounds__(256) void prepack_B(
    const float* __restrict__ W, ull* __restrict__ out)
{
    int i = blockIdx.x * 256 + threadIdx.x;      // 0..8191
    int e = i & 1, u = i >> 1;
    int t = u & 3, g = (u >> 2) & 7, jj = (u >> 5) & 3, kk = u >> 7;
    int n  = (2 * jj + e) * 8 + g;
    int k1 = kk * 8 + t;
    unsigned lo = f2tf32(W[(size_t)k1 * 64 + n]);
    unsigned hi = f2tf32(W[(size_t)(k1 + 4) * 64 + n]);
    out[i] = ((ull)hi << 32) | (ull)lo;
}

// ---------------------------------------------------------------------------
// Tensor-core GEMM: C[M,64] = A[M,256] @ W[256,64] + bias  (tf32 HMMA)
// 256 threads, BM=128 rows; warp w owns m16 tile rows w*16..w*16+15, all 64 n.
// 4-stage cp.async pipeline, 104KB smem -> 2 CTAs/SM (16 warps).
// ---------------------------------------------------------------------------
#define BM        128
#define STAGES    4
#define ASTRIDE   36                           // floats per padded A row
#define AS_STAGE  (BM * ASTRIDE)               // 4608 floats = 18 KB
#define BS_STAGE  1024                         // ulls = 8 KB
#define SMEM_A_BYTES (STAGES * AS_STAGE * 4)   // 73728
#define SMEM_B_BYTES (STAGES * BS_STAGE * 8)   // 32768
#define GEMM_SMEM    (SMEM_A_BYTES + SMEM_B_BYTES)   // 106496

__global__ __launch_bounds__(256, 2) void gemm_tc(
    const float* __restrict__ A, const ull* __restrict__ Bpack,
    const float* __restrict__ bias, float* __restrict__ C, int M)
{
    extern __shared__ char smem_raw[];
    float* As = (float*)smem_raw;
    ull*   Bs = (ull*)(smem_raw + SMEM_A_BYTES);
    const unsigned sA = (unsigned)__cvta_generic_to_shared(As);
    const unsigned sB = (unsigned)__cvta_generic_to_shared(Bs);

    const int tid  = threadIdx.x;
    const int lane = tid & 31;
    const int warp = tid >> 5;
    const int g = lane >> 2;          // 0..7
    const int t = lane & 3;           // 0..3
    const int rowBase = blockIdx.x * BM;

    const int segA = lane & 7;        // 16B segment within a row's 32-k chunk
    const int rA   = lane >> 3;       // row sub-index (+4*it)

    float acc[8][4];
#pragma unroll
    for (int j = 0; j < 8; j++)
#pragma unroll
        for (int q = 0; q < 4; q++) acc[j][q] = 0.f;

#define ISSUE_CHUNK(c, stage)                                                  \
    do {                                                                       \
        _Pragma("unroll")                                                      \
        for (int it = 0; it < 4; it++) {                                       \
            int rin  = warp * 16 + it * 4 + rA;                                \
            int grow = rowBase + rin;                                          \
            const float* srcp = A + (size_t)grow * K_IN + (c) * 32 + segA * 4; \
            unsigned sz  = (grow < M) ? 16u : 0u;                              \
            unsigned dst = sA + ((stage) * AS_STAGE + rin * ASTRIDE            \
                                 + segA * 4) * 4;                              \
            cp_async16(dst, srcp, sz);                                         \
        }                                                                      \
        _Pragma("unroll")                                                      \
        for (int j = 0; j < 2; j++) {                                          \
            int chunk = tid + j * 256;                                         \
            const ull* srcb = Bpack + (size_t)(c) * 1024 + chunk * 2;          \
            unsigned dst = sB + ((stage) * BS_STAGE + chunk * 2) * 8;          \
            cp_async16(dst, srcb, 16u);                                        \
        }                                                                      \
    } while (0)

    // prologue: stages 0..2
#pragma unroll
    for (int c = 0; c < 3; c++) {
        ISSUE_CHUNK(c, c);
        asm volatile("cp.async.commit_group;" ::: "memory");
    }

    for (int c = 0; c < 8; c++) {
        asm volatile("cp.async.wait_group 2;" ::: "memory");
        __syncthreads();                          // chunk c visible CTA-wide

        if (c + 3 < 8) ISSUE_CHUNK(c + 3, (c + 3) & 3);
        asm volatile("cp.async.commit_group;" ::: "memory");

        const int s = c & 3;
        const float* as = As + s * AS_STAGE + (warp * 16) * ASTRIDE;
        const uint4* bs = (const uint4*)(Bs + s * BS_STAGE);
#pragma unroll
        for (int kl = 0; kl < 4; kl++) {
            uint4 bv[4];
#pragma unroll
            for (int jj = 0; jj < 4; jj++)
                bv[jj] = bs[kl * 128 + jj * 32 + g * 4 + t];   // conflict-free
            unsigned a0 = f2tf32(as[(g)     * ASTRIDE + kl * 8 + t]);
            unsigned a1 = f2tf32(as[(g + 8) * ASTRIDE + kl * 8 + t]);
            unsigned a2 = f2tf32(as[(g)     * ASTRIDE + kl * 8 + t + 4]);
            unsigned a3 = f2tf32(as[(g + 8) * ASTRIDE + kl * 8 + t + 4]);
#pragma unroll
            for (int jj = 0; jj < 4; jj++) {
                asm volatile(
                    "mma.sync.aligned.m16n8k8.row.col.f32.tf32.tf32.f32 "
                    "{%0,%1,%2,%3}, {%4,%5,%6,%7}, {%8,%9}, {%0,%1,%2,%3};"
                    : "+f"(acc[2 * jj][0]), "+f"(acc[2 * jj][1]),
                      "+f"(acc[2 * jj][2]), "+f"(acc[2 * jj][3])
                    : "r"(a0), "r"(a1), "r"(a2), "r"(a3),
                      "r"(bv[jj].x), "r"(bv[jj].y));
                asm volatile(
                    "mma.sync.aligned.m16n8k8.row.col.f32.tf32.tf32.f32 "
                    "{%0,%1,%2,%3}, {%4,%5,%6,%7}, {%8,%9}, {%0,%1,%2,%3};"
                    : "+f"(acc[2 * jj + 1][0]), "+f"(acc[2 * jj + 1][1]),
                      "+f"(acc[2 * jj + 1][2]), "+f"(acc[2 * jj + 1][3])
                    : "r"(a0), "r"(a1), "r"(a2), "r"(a3),
                      "r"(bv[jj].z), "r"(bv[jj].w));
            }
        }
    }

    // epilogue: bias + store (rows g, g+8 of this warp's m16 tile)
    int r0 = rowBase + warp * 16 + g;
#pragma unroll
    for (int j = 0; j < 8; j++) {
        int col = j * 8 + 2 * t;
        float b0 = __ldg(&bias[col]), b1 = __ldg(&bias[col + 1]);
        if (r0 < M)
            *(float2*)&C[(size_t)r0 * N_OUT + col] =
                make_float2(acc[j][0] + b0, acc[j][1] + b1);
        if (r0 + 8 < M)
            *(float2*)&C[(size_t)(r0 + 8) * N_OUT + col] =
                make_float2(acc[j][2] + b0, acc[j][3] + b1);
    }
#undef ISSUE_CHUNK
}

// ---------------------------------------------------------------------------
// In-degree accumulation, 4 edges per thread (int4 load + 4 REDs in flight).
// ---------------------------------------------------------------------------
__global__ __launch_bounds__(256) void degree_kernel(
    const int* __restrict__ dst, float* __restrict__ deg, int E)
{
    int base = (blockIdx.x * 256 + threadIdx.x) * 4;
    if (base + 3 < E) {
        int4 d = *(const int4*)(dst + base);
        atomicAdd(&deg[d.x], 1.0f);
        atomicAdd(&deg[d.y], 1.0f);
        atomicAdd(&deg[d.z], 1.0f);
        atomicAdd(&deg[d.w], 1.0f);
    } else {
        for (int e = base; e < E; e++) atomicAdd(&deg[dst[e]], 1.0f);
    }
}

// ---------------------------------------------------------------------------
// Edge scatter with mean folded in: out[d] += Wh[s] * (1/deg[d]).
// 16 threads per edge-lane, 8 edges per thread: 8 independent gather+RED
// chains in flight against L2 latency.
// ---------------------------------------------------------------------------
#define SC_ILP 8
__global__ __launch_bounds__(256) void scatter_mean_kernel(
    const float* __restrict__ Wh, const int* __restrict__ src,
    const int* __restrict__ dst, const float* __restrict__ deg,
    float* __restrict__ out, int E)
{
    const int seg = (E + SC_ILP - 1) / SC_ILP;
    int t = blockIdx.x * 256 + threadIdx.x;
    int e0 = t >> 4;
    if (e0 >= seg) return;
    int lane = t & 15;

    int  s_[SC_ILP], d_[SC_ILP];
    bool has[SC_ILP];
#pragma unroll
    for (int i = 0; i < SC_ILP; i++) {
        int ei = e0 + i * seg;
        has[i] = ei < E;
        s_[i]  = has[i] ? __ldg(&src[ei]) : 0;
        d_[i]  = has[i] ? __ldg(&dst[ei]) : 0;
    }
    float4 v[SC_ILP];
    float  inv[SC_ILP];
#pragma unroll
    for (int i = 0; i < SC_ILP; i++) {
        if (has[i]) {
            v[i]   = __ldg(((const float4*)(Wh + (size_t)s_[i] * N_OUT)) + lane);
            inv[i] = __frcp_rn(__ldg(&deg[d_[i]]));
        }
    }
#pragma unroll
    for (int i = 0; i < SC_ILP; i++) {
        if (has[i]) {
            float4 w = v[i];
            w.x *= inv[i]; w.y *= inv[i]; w.z *= inv[i]; w.w *= inv[i];
            float4* p = ((float4*)(out + (size_t)d_[i] * N_OUT)) + lane;
            asm volatile("red.global.add.v4.f32 [%0], {%1,%2,%3,%4};"
                         :: "l"(p), "f"(w.x), "f"(w.y), "f"(w.z), "f"(w.w)
                         : "memory");
        }
    }
}

// ---------------------------------------------------------------------------
extern "C" void kernel_launch(void* const* d_in, const int* in_sizes, int n_in,
                              void* d_out, int out_size)
{
    const float* user_feats  = (const float*)d_in[0];
    const float* photo_feats = (const float*)d_in[1];
    const float* W_likes     = (const float*)d_in[2];
    const float* b_likes     = (const float*)d_in[3];
    const float* W_likedby   = (const float*)d_in[4];
    const float* b_likedby   = (const float*)d_in[5];
    const int*   likes_src   = (const int*)d_in[6];
    const int*   likes_dst   = (const int*)d_in[7];
    const int*   likedby_src = (const int*)d_in[8];
    const int*   likedby_dst = (const int*)d_in[9];
    const int E1 = in_sizes[6];
    const int E2 = in_sizes[8];

    float* out_user  = (float*)d_out;                            // [N_USER, 64]
    float* out_photo = (float*)d_out + (size_t)N_USER * N_OUT;   // [N_PHOTO, 64]

    float *wh_user, *wh_photo, *deg_user, *deg_photo;
    ull *bp_likes, *bp_likedby;
    cudaGetSymbolAddress((void**)&wh_user,  g_Wh_user);
    cudaGetSymbolAddress((void**)&wh_photo, g_Wh_photo);
    cudaGetSymbolAddress((void**)&deg_user,  g_deg_user);
    cudaGetSymbolAddress((void**)&deg_photo, g_deg_photo);
    cudaGetSymbolAddress((void**)&bp_likes,   g_Bpack_likes);
    cudaGetSymbolAddress((void**)&bp_likedby, g_Bpack_likedby);

    // One-time setup (first call is the uncaptured correctness run).
    static cudaStream_t s_aux = nullptr, s_sc = nullptr;
    static cudaEvent_t evStart, evAux, evPP, evG1, evSc1;
    if (!s_aux) {
        cudaStreamCreateWithFlags(&s_aux, cudaStreamNonBlocking);
        cudaStreamCreateWithFlags(&s_sc,  cudaStreamNonBlocking);
        cudaEventCreateWithFlags(&evStart, cudaEventDisableTiming);
        cudaEventCreateWithFlags(&evAux,   cudaEventDisableTiming);
        cudaEventCreateWithFlags(&evPP,    cudaEventDisableTiming);
        cudaEventCreateWithFlags(&evG1,    cudaEventDisableTiming);
        cudaEventCreateWithFlags(&evSc1,   cudaEventDisableTiming);
        cudaFuncSetAttribute(gemm_tc,
                             cudaFuncAttributeMaxDynamicSharedMemorySize,
                             GEMM_SMEM);
    }

    // Fork helper streams off the capture (main) stream.
    cudaEventRecord(evStart, 0);
    cudaStreamWaitEvent(s_aux, evStart, 0);
    cudaStreamWaitEvent(s_sc,  evStart, 0);

    // s_sc front: weight prepack (so GEMMs aren't serialized behind it).
    prepack_B<<<32, 256, 0, s_sc>>>(W_likes,   bp_likes);
    prepack_B<<<32, 256, 0, s_sc>>>(W_likedby, bp_likedby);
    cudaEventRecord(evPP, s_sc);

    // Aux path: zeroing + degrees (independent of the GEMMs).
    cudaMemsetAsync(d_out, 0, (size_t)out_size * sizeof(float), s_aux);
    cudaMemsetAsync(deg_user,  0, (size_t)N_USER  * sizeof(float), s_aux);
    cudaMemsetAsync(deg_photo, 0, (size_t)N_PHOTO * sizeof(float), s_aux);
    degree_kernel<<<(E1 + 1023) / 1024, 256, 0, s_aux>>>(likes_dst,   deg_photo, E1);
    degree_kernel<<<(E2 + 1023) / 1024, 256, 0, s_aux>>>(likedby_dst, deg_user,  E2);
    cudaEventRecord(evAux, s_aux);

    // Main path: the two projections (after prepack).
    cudaStreamWaitEvent(0, evPP, 0);
    gemm_tc<<<(N_USER + BM - 1) / BM, 256, GEMM_SMEM>>>(
        user_feats,  bp_likes,   b_likes,   wh_user,  N_USER);
    cudaEventRecord(evG1, 0);
    gemm_tc<<<(N_PHOTO + BM - 1) / BM, 256, GEMM_SMEM>>>(
        photo_feats, bp_likedby, b_likedby, wh_photo, N_PHOTO);

    // scatter1 (photo outputs) overlaps gemm_photo on its own stream.
    cudaStreamWaitEvent(s_sc, evG1, 0);
    cudaStreamWaitEvent(s_sc, evAux, 0);
    {
        int seg1 = (E1 + SC_ILP - 1) / SC_ILP;
        scatter_mean_kernel<<<((size_t)seg1 * 16 + 255) / 256, 256, 0, s_sc>>>(
            wh_user, likes_src, likes_dst, deg_photo, out_photo, E1);
    }
    cudaEventRecord(evSc1, s_sc);

    // scatter2 (user outputs) on the main stream after gemm_photo.
    cudaStreamWaitEvent(0, evAux, 0);
    {
        int seg2 = (E2 + SC_ILP - 1) / SC_ILP;
        scatter_mean_kernel<<<((size_t)seg2 * 16 + 255) / 256, 256>>>(
            wh_photo, likedby_src, likedby_dst, deg_user, out_user, E2);
    }

    // Join everything back onto the capture stream.
    cudaStreamWaitEvent(0, evSc1, 0);
}

// round 7
// speedup vs baseline: 1.1151x; 1.1151x over previous
#include <cuda_runtime.h>
#include <cstdint>

#define N_USER  100000
#define N_PHOTO 200000
#define K_IN    256
#define N_OUT   64

typedef unsigned long long ull;

// Scratch (static device globals; no allocs).
__device__ float g_Wh_user [(size_t)N_USER  * N_OUT];   // 25.6 MB
__device__ float g_Wh_photo[(size_t)N_PHOTO * N_OUT];   // 51.2 MB
__device__ float g_deg_user [N_USER];
__device__ float g_deg_photo[N_PHOTO];
__device__ ull   g_Bpack_likes  [8192];                 // packed tf32 W (64 KB)
__device__ ull   g_Bpack_likedby[8192];

__device__ __forceinline__ unsigned f2tf32(float f) {
    unsigned r;
    asm("cvt.rna.tf32.f32 %0, %1;" : "=r"(r) : "f"(f));
    return r;
}

__device__ __forceinline__ void cp_async16(unsigned dst_smem, const void* src,
                                           unsigned src_bytes) {
    asm volatile("cp.async.cg.shared.global [%0], [%1], 16, %2;"
                 :: "r"(dst_smem), "l"(src), "r"(src_bytes) : "memory");
}

// ---------------------------------------------------------------------------
// Prepack W[256,64] -> fragment-ordered tf32 ull table.
// ull index i: e = i&1; u = i>>1; t = u&3; g = (u>>2)&7; jj = (u>>5)&3; kk = u>>7.
// value = pack( tf32 W[kk*8+t][n], tf32 W[kk*8+t+4][n] ), n = (2jj+e)*8 + g.
// A warp's B fragment (kstep kk, quad t, n-pair jj) = one LDS.128 at uint4
// index kk*128 + jj*32 + g*4 + t  -> phase banks g*16+t*4: conflict-FREE.
// ---------------------------------------------------------------------------
__global__ __launch_bounds__(256) void prepack_B(
    const float* __restrict__ W, ull* __restrict__ out)
{
    int i = blockIdx.x * 256 + threadIdx.x;      // 0..8191
    int e = i & 1, u = i >> 1;
    int t = u & 3, g = (u >> 2) & 7, jj = (u >> 5) & 3, kk = u >> 7;
    int n  = (2 * jj + e) * 8 + g;
    int k1 = kk * 8 + t;
    unsigned lo = f2tf32(W[(size_t)k1 * 64 + n]);
    unsigned hi = f2tf32(W[(size_t)(k1 + 4) * 64 + n]);
    out[i] = ((ull)hi << 32) | (ull)lo;
}

// ---------------------------------------------------------------------------
// Tensor-core GEMM: C[M,64] = A[M,256] @ W[256,64] + bias  (tf32 HMMA)
// 256 threads, BM=256 rows; warp w owns rows w*32..w*32+31 (2 m16 tiles that
// SHARE B fragments). 3-stage cp.async pipeline (A 36KB + B 8KB per stage).
// ---------------------------------------------------------------------------
#define BM        256
#define STAGES    3
#define ASTRIDE   36                           // floats per padded A row
#define AS_STAGE  (BM * ASTRIDE)               // 9216 floats = 36 KB
#define BS_STAGE  1024                         // ulls = 8 KB
#define SMEM_A_BYTES (STAGES * AS_STAGE * 4)   // 110592
#define SMEM_B_BYTES (STAGES * BS_STAGE * 8)   // 24576
#define GEMM_SMEM    (SMEM_A_BYTES + SMEM_B_BYTES)

__global__ __launch_bounds__(256, 1) void gemm_tc(
    const float* __restrict__ A, const ull* __restrict__ Bpack,
    const float* __restrict__ bias, float* __restrict__ C, int M)
{
    extern __shared__ char smem_raw[];
    float* As = (float*)smem_raw;
    ull*   Bs = (ull*)(smem_raw + SMEM_A_BYTES);
    const unsigned sA = (unsigned)__cvta_generic_to_shared(As);
    const unsigned sB = (unsigned)__cvta_generic_to_shared(Bs);

    const int tid  = threadIdx.x;
    const int lane = tid & 31;
    const int warp = tid >> 5;
    const int g = lane >> 2;          // 0..7
    const int t = lane & 3;           // 0..3
    const int rowBase = blockIdx.x * BM;

    const int segA = lane & 7;        // 16B segment within a row's 32-k chunk
    const int rA   = lane >> 3;       // row sub-index (+4*it)

    float acc[2][8][4];
#pragma unroll
    for (int m = 0; m < 2; m++)
#pragma unroll
        for (int j = 0; j < 8; j++)
#pragma unroll
            for (int q = 0; q < 4; q++) acc[m][j][q] = 0.f;

#define ISSUE_CHUNK(c, stage)                                                  \
    do {                                                                       \
        _Pragma("unroll")                                                      \
        for (int it = 0; it < 8; it++) {                                       \
            int rin  = warp * 32 + it * 4 + rA;                                \
            int grow = rowBase + rin;                                          \
            const float* srcp = A + (size_t)grow * K_IN + (c) * 32 + segA * 4; \
            unsigned sz  = (grow < M) ? 16u : 0u;                              \
            unsigned dst = sA + ((stage) * AS_STAGE + rin * ASTRIDE            \
                                 + segA * 4) * 4;                              \
            cp_async16(dst, srcp, sz);                                         \
        }                                                                      \
        _Pragma("unroll")                                                      \
        for (int j = 0; j < 2; j++) {                                          \
            int chunk = tid + j * 256;                                         \
            const ull* srcb = Bpack + (size_t)(c) * 1024 + chunk * 2;          \
            unsigned dst = sB + ((stage) * BS_STAGE + chunk * 2) * 8;          \
            cp_async16(dst, srcb, 16u);                                        \
        }                                                                      \
    } while (0)

    // prologue: stages 0..1
    ISSUE_CHUNK(0, 0);
    asm volatile("cp.async.commit_group;" ::: "memory");
    ISSUE_CHUNK(1, 1);
    asm volatile("cp.async.commit_group;" ::: "memory");

    for (int c = 0; c < 8; c++) {
        asm volatile("cp.async.wait_group 1;" ::: "memory");
        __syncthreads();                          // chunk c visible CTA-wide

        if (c + 2 < 8) {
            int st = (c + 2) % STAGES;
            ISSUE_CHUNK(c + 2, st);
        }
        asm volatile("cp.async.commit_group;" ::: "memory");

        const int s = c % STAGES;
        const float* as = As + s * AS_STAGE + (warp * 32) * ASTRIDE;
        const uint4* bs = (const uint4*)(Bs + s * BS_STAGE);
#pragma unroll
        for (int kl = 0; kl < 4; kl++) {
            uint4 bv[4];
#pragma unroll
            for (int jj = 0; jj < 4; jj++)
                bv[jj] = bs[kl * 128 + jj * 32 + g * 4 + t];   // conflict-free
#pragma unroll
            for (int m = 0; m < 2; m++) {
                const float* am = as + m * 16 * ASTRIDE;
                unsigned a0 = f2tf32(am[(g)     * ASTRIDE + kl * 8 + t]);
                unsigned a1 = f2tf32(am[(g + 8) * ASTRIDE + kl * 8 + t]);
                unsigned a2 = f2tf32(am[(g)     * ASTRIDE + kl * 8 + t + 4]);
                unsigned a3 = f2tf32(am[(g + 8) * ASTRIDE + kl * 8 + t + 4]);
#pragma unroll
                for (int jj = 0; jj < 4; jj++) {
                    asm volatile(
                        "mma.sync.aligned.m16n8k8.row.col.f32.tf32.tf32.f32 "
                        "{%0,%1,%2,%3}, {%4,%5,%6,%7}, {%8,%9}, {%0,%1,%2,%3};"
                        : "+f"(acc[m][2 * jj][0]), "+f"(acc[m][2 * jj][1]),
                          "+f"(acc[m][2 * jj][2]), "+f"(acc[m][2 * jj][3])
                        : "r"(a0), "r"(a1), "r"(a2), "r"(a3),
                          "r"(bv[jj].x), "r"(bv[jj].y));
                    asm volatile(
                        "mma.sync.aligned.m16n8k8.row.col.f32.tf32.tf32.f32 "
                        "{%0,%1,%2,%3}, {%4,%5,%6,%7}, {%8,%9}, {%0,%1,%2,%3};"
                        : "+f"(acc[m][2 * jj + 1][0]), "+f"(acc[m][2 * jj + 1][1]),
                          "+f"(acc[m][2 * jj + 1][2]), "+f"(acc[m][2 * jj + 1][3])
                        : "r"(a0), "r"(a1), "r"(a2), "r"(a3),
                          "r"(bv[jj].z), "r"(bv[jj].w));
                }
            }
        }
    }

    // epilogue: bias + store
#pragma unroll
    for (int m = 0; m < 2; m++) {
        int r0 = rowBase + warp * 32 + m * 16 + g;
#pragma unroll
        for (int j = 0; j < 8; j++) {
            int col = j * 8 + 2 * t;
            float b0 = __ldg(&bias[col]), b1 = __ldg(&bias[col + 1]);
            if (r0 < M)
                *(float2*)&C[(size_t)r0 * N_OUT + col] =
                    make_float2(acc[m][j][0] + b0, acc[m][j][1] + b1);
            if (r0 + 8 < M)
                *(float2*)&C[(size_t)(r0 + 8) * N_OUT + col] =
                    make_float2(acc[m][j][2] + b0, acc[m][j][3] + b1);
        }
    }
#undef ISSUE_CHUNK
}

// ---------------------------------------------------------------------------
// In-degree accumulation, 4 edges per thread (int4 load + 4 REDs in flight).
// ---------------------------------------------------------------------------
__global__ __launch_bounds__(256) void degree_kernel(
    const int* __restrict__ dst, float* __restrict__ deg, int E)
{
    int base = (blockIdx.x * 256 + threadIdx.x) * 4;
    if (base + 3 < E) {
        int4 d = *(const int4*)(dst + base);
        atomicAdd(&deg[d.x], 1.0f);
        atomicAdd(&deg[d.y], 1.0f);
        atomicAdd(&deg[d.z], 1.0f);
        atomicAdd(&deg[d.w], 1.0f);
    } else {
        for (int e = base; e < E; e++) atomicAdd(&deg[dst[e]], 1.0f);
    }
}

// ---------------------------------------------------------------------------
// Edge scatter with mean folded in: out[d] += Wh[s] * (1/deg[d]).
// 16 threads per edge-lane, 4 edges per thread (4 independent gather+RED
// chains in flight against L2 latency).
// ---------------------------------------------------------------------------
__global__ __launch_bounds__(256) void scatter_mean_kernel(
    const float* __restrict__ Wh, const int* __restrict__ src,
    const int* __restrict__ dst, const float* __restrict__ deg,
    float* __restrict__ out, int E)
{
    const int quarter = (E + 3) >> 2;
    int t = blockIdx.x * 256 + threadIdx.x;
    int e0 = t >> 4;
    if (e0 >= quarter) return;
    int lane = t & 15;

    int    ei[4];
    bool   has[4];
    int    s_[4], d_[4];
#pragma unroll
    for (int i = 0; i < 4; i++) {
        ei[i]  = e0 + i * quarter;
        has[i] = ei[i] < E;
        s_[i]  = has[i] ? __ldg(&src[ei[i]]) : 0;
        d_[i]  = has[i] ? __ldg(&dst[ei[i]]) : 0;
    }
    float4 v[4];
    float  inv[4];
#pragma unroll
    for (int i = 0; i < 4; i++) {
        if (has[i]) {
            v[i]   = __ldg(((const float4*)(Wh + (size_t)s_[i] * N_OUT)) + lane);
            inv[i] = __frcp_rn(__ldg(&deg[d_[i]]));
        }
    }
#pragma unroll
    for (int i = 0; i < 4; i++) {
        if (has[i]) {
            float4 w = v[i];
            w.x *= inv[i]; w.y *= inv[i]; w.z *= inv[i]; w.w *= inv[i];
            float4* p = ((float4*)(out + (size_t)d_[i] * N_OUT)) + lane;
            asm volatile("red.global.add.v4.f32 [%0], {%1,%2,%3,%4};"
                         :: "l"(p), "f"(w.x), "f"(w.y), "f"(w.z), "f"(w.w)
                         : "memory");
        }
    }
}

// ---------------------------------------------------------------------------
extern "C" void kernel_launch(void* const* d_in, const int* in_sizes, int n_in,
                              void* d_out, int out_size)
{
    const float* user_feats  = (const float*)d_in[0];
    const float* photo_feats = (const float*)d_in[1];
    const float* W_likes     = (const float*)d_in[2];
    const float* b_likes     = (const float*)d_in[3];
    const float* W_likedby   = (const float*)d_in[4];
    const float* b_likedby   = (const float*)d_in[5];
    const int*   likes_src   = (const int*)d_in[6];
    const int*   likes_dst   = (const int*)d_in[7];
    const int*   likedby_src = (const int*)d_in[8];
    const int*   likedby_dst = (const int*)d_in[9];
    const int E1 = in_sizes[6];
    const int E2 = in_sizes[8];

    float* out_user  = (float*)d_out;                            // [N_USER, 64]
    float* out_photo = (float*)d_out + (size_t)N_USER * N_OUT;   // [N_PHOTO, 64]

    float *wh_user, *wh_photo, *deg_user, *deg_photo;
    ull *bp_likes, *bp_likedby;
    cudaGetSymbolAddress((void**)&wh_user,  g_Wh_user);
    cudaGetSymbolAddress((void**)&wh_photo, g_Wh_photo);
    cudaGetSymbolAddress((void**)&deg_user,  g_deg_user);
    cudaGetSymbolAddress((void**)&deg_photo, g_deg_photo);
    cudaGetSymbolAddress((void**)&bp_likes,   g_Bpack_likes);
    cudaGetSymbolAddress((void**)&bp_likedby, g_Bpack_likedby);

    // One-time setup (first call is the uncaptured correctness run).
    static cudaStream_t s_aux = nullptr, s_b = nullptr;
    static cudaEvent_t evStart, evAux, evG1, evSc1;
    if (!s_aux) {
        cudaStreamCreateWithFlags(&s_aux, cudaStreamNonBlocking);
        cudaStreamCreateWithFlags(&s_b,   cudaStreamNonBlocking);
        cudaEventCreateWithFlags(&evStart, cudaEventDisableTiming);
        cudaEventCreateWithFlags(&evAux,   cudaEventDisableTiming);
        cudaEventCreateWithFlags(&evG1,    cudaEventDisableTiming);
        cudaEventCreateWithFlags(&evSc1,   cudaEventDisableTiming);
        cudaFuncSetAttribute(gemm_tc,
                             cudaFuncAttributeMaxDynamicSharedMemorySize,
                             GEMM_SMEM);
    }

    // Fork helper streams off the capture (main) stream.
    cudaEventRecord(evStart, 0);
    cudaStreamWaitEvent(s_aux, evStart, 0);
    cudaStreamWaitEvent(s_b,   evStart, 0);

    // Aux path: zeroing + degrees (independent of the GEMMs).
    cudaMemsetAsync(d_out, 0, (size_t)out_size * sizeof(float), s_aux);
    cudaMemsetAsync(deg_user,  0, (size_t)N_USER  * sizeof(float), s_aux);
    cudaMemsetAsync(deg_photo, 0, (size_t)N_PHOTO * sizeof(float), s_aux);
    degree_kernel<<<(E1 / 4 + 256) / 256 + 1, 256, 0, s_aux>>>(likes_dst,   deg_photo, E1);
    degree_kernel<<<(E2 / 4 + 256) / 256 + 1, 256, 0, s_aux>>>(likedby_dst, deg_user,  E2);
    cudaEventRecord(evAux, s_aux);

    // Stream MAIN: prepack(likes) -> gemm_user -> scatter1 (photo outputs).
    // Stream B:   prepack(likedby) -> gemm_photo -> scatter2 (user outputs).
    // The two GEMMs are independent and run CONCURRENTLY (packs CTA waves,
    // removes serialization bubbles between the launches).
    prepack_B<<<32, 256>>>(W_likes, bp_likes);
    prepack_B<<<32, 256, 0, s_b>>>(W_likedby, bp_likedby);

    gemm_tc<<<(N_USER + BM - 1) / BM, 256, GEMM_SMEM>>>(
        user_feats,  bp_likes,   b_likes,   wh_user,  N_USER);
    gemm_tc<<<(N_PHOTO + BM - 1) / BM, 256, GEMM_SMEM, s_b>>>(
        photo_feats, bp_likedby, b_likedby, wh_photo, N_PHOTO);

    // scatter1: needs wh_user (main) + degrees.
    cudaStreamWaitEvent(0, evAux, 0);
    {
        int q1 = (E1 + 3) >> 2;
        scatter_mean_kernel<<<((size_t)q1 * 16 + 255) / 256, 256>>>(
            wh_user, likes_src, likes_dst, deg_photo, out_photo, E1);
    }
    cudaEventRecord(evSc1, 0);

    // scatter2: needs wh_photo (s_b) + degrees.
    cudaStreamWaitEvent(s_b, evAux, 0);
    {
        int q2 = (E2 + 3) >> 2;
        scatter_mean_kernel<<<((size_t)q2 * 16 + 255) / 256, 256, 0, s_b>>>(
            wh_photo, likedby_src, likedby_dst, deg_user, out_user, E2);
    }
    cudaEventRecord(evG1, s_b);

    // Join both paths back onto the capture stream.
    cudaStreamWaitEvent(0, evG1, 0);
}